// round 2
// baseline (speedup 1.0000x reference)
#include <cuda_runtime.h>
#include <cstdint>

// RandomPixelMapping: out[b,c,y,x] = table[b,c, clip(rint(x*255), 0, 255)]
// x: [64,3,512,512] f32, table: [64,3,256] f32, out: [64,3,512,512] f32.
// Pure HBM-streaming gather; per-(b,c) 256-entry LUT in shared memory.
// R2: MLP=8 vec4 per thread + evict-first streaming loads/stores.

#define PLANE_ELEMS    (512 * 512)          // 262144 elems per (b,c) plane
#define VEC_PER_PLANE  (PLANE_ELEMS / 4)    // 65536 float4
#define THREADS        256
#define CHUNKS         32                   // blocks per plane
#define VEC_PER_BLOCK  (VEC_PER_PLANE / CHUNKS)      // 2048 float4 per block
#define VEC_PER_THREAD (VEC_PER_BLOCK / THREADS)     // 8 float4 per thread

__device__ __forceinline__ float4 ldcs_f4(const float4* p) {
    float4 v;
    asm volatile("ld.global.cs.v4.f32 {%0,%1,%2,%3}, [%4];"
                 : "=f"(v.x), "=f"(v.y), "=f"(v.z), "=f"(v.w) : "l"(p));
    return v;
}

__device__ __forceinline__ void stcs_f4(float4* p, float4 v) {
    asm volatile("st.global.cs.v4.f32 [%0], {%1,%2,%3,%4};"
                 :: "l"(p), "f"(v.x), "f"(v.y), "f"(v.z), "f"(v.w) : "memory");
}

__global__ __launch_bounds__(THREADS)
void RandomPixelMapping_19593640805006_kernel(
    const float4* __restrict__ x,
    const float*  __restrict__ table,
    float4*       __restrict__ out)
{
    __shared__ float lut[256];

    const int plane = blockIdx.y;                 // 0..191  (b*3 + c)
    lut[threadIdx.x] = table[plane * 256 + threadIdx.x];
    __syncthreads();

    const size_t base = (size_t)plane * VEC_PER_PLANE
                      + (size_t)blockIdx.x * VEC_PER_BLOCK
                      + threadIdx.x;

    // Front-batch 8 independent vec4 streaming loads (MLP=8), then gather+store.
    float4 v[VEC_PER_THREAD];
#pragma unroll
    for (int j = 0; j < VEC_PER_THREAD; ++j)
        v[j] = ldcs_f4(x + base + (size_t)j * THREADS);

#pragma unroll
    for (int j = 0; j < VEC_PER_THREAD; ++j) {
        float4 r;
        int i0 = __float2int_rn(v[j].x * 255.0f);
        int i1 = __float2int_rn(v[j].y * 255.0f);
        int i2 = __float2int_rn(v[j].z * 255.0f);
        int i3 = __float2int_rn(v[j].w * 255.0f);
        i0 = min(max(i0, 0), 255);
        i1 = min(max(i1, 0), 255);
        i2 = min(max(i2, 0), 255);
        i3 = min(max(i3, 0), 255);
        r.x = lut[i0];
        r.y = lut[i1];
        r.z = lut[i2];
        r.w = lut[i3];
        stcs_f4(out + base + (size_t)j * THREADS, r);
    }
}

extern "C" void kernel_launch(void* const* d_in, const int* in_sizes, int n_in,
                              void* d_out, int out_size)
{
    const float4* x     = (const float4*)d_in[0];
    const float*  table = (const float*) d_in[1];
    float4*       out   = (float4*)d_out;

    dim3 grid(CHUNKS, 64 * 3);   // 32 chunks x 192 planes = 6144 CTAs
    RandomPixelMapping_19593640805006_kernel<<<grid, THREADS>>>(x, table, out);
}

// round 3
// speedup vs baseline: 1.0005x; 1.0005x over previous
#include <cuda_runtime.h>
#include <cstdint>

// RandomPixelMapping: out[b,c,y,x] = table[b,c, clip(rint(x*255), 0, 255)]
// x: [64,3,512,512] f32, table: [64,3,256] f32, out: [64,3,512,512] f32.
// R3: bank-replicated LUT (lut[idx][lane], 32 KB smem) -> conflict-free LDS.

#define PLANE_ELEMS    (512 * 512)          // 262144 elems per (b,c) plane
#define VEC_PER_PLANE  (PLANE_ELEMS / 4)    // 65536 float4
#define THREADS        256
#define CHUNKS         32                   // blocks per plane
#define VEC_PER_BLOCK  (VEC_PER_PLANE / CHUNKS)      // 2048 float4 per block
#define VEC_PER_THREAD (VEC_PER_BLOCK / THREADS)     // 8 float4 per thread

__global__ __launch_bounds__(THREADS)
void RandomPixelMapping_19593640805006_kernel(
    const float4* __restrict__ x,
    const float*  __restrict__ table,
    float4*       __restrict__ out)
{
    // Bank-replicated LUT: lut[idx][lane] holds table[idx] for every lane.
    // Lane l always reads column l -> bank l -> zero conflicts.
    __shared__ float lut[256][32];

    const int tid  = threadIdx.x;
    const int lane = tid & 31;
    const int plane = blockIdx.y;                 // 0..191  (b*3 + c)

    // Fill: thread tid owns row tid. Rotate column by lane so each warp's
    // 32 simultaneous STS hit 32 distinct banks.
    {
        const float t = table[plane * 256 + tid];
#pragma unroll
        for (int j = 0; j < 32; ++j)
            lut[tid][(j + lane) & 31] = t;
    }
    __syncthreads();

    const size_t base = (size_t)plane * VEC_PER_PLANE
                      + (size_t)blockIdx.x * VEC_PER_BLOCK
                      + tid;

    // Front-batch 8 independent vec4 loads (MLP=8), then conflict-free gather.
    float4 v[VEC_PER_THREAD];
#pragma unroll
    for (int j = 0; j < VEC_PER_THREAD; ++j)
        v[j] = x[base + (size_t)j * THREADS];

#pragma unroll
    for (int j = 0; j < VEC_PER_THREAD; ++j) {
        float4 r;
        int i0 = __float2int_rn(v[j].x * 255.0f);
        int i1 = __float2int_rn(v[j].y * 255.0f);
        int i2 = __float2int_rn(v[j].z * 255.0f);
        int i3 = __float2int_rn(v[j].w * 255.0f);
        i0 = min(max(i0, 0), 255);
        i1 = min(max(i1, 0), 255);
        i2 = min(max(i2, 0), 255);
        i3 = min(max(i3, 0), 255);
        r.x = lut[i0][lane];
        r.y = lut[i1][lane];
        r.z = lut[i2][lane];
        r.w = lut[i3][lane];
        out[base + (size_t)j * THREADS] = r;
    }
}

extern "C" void kernel_launch(void* const* d_in, const int* in_sizes, int n_in,
                              void* d_out, int out_size)
{
    const float4* x     = (const float4*)d_in[0];
    const float*  table = (const float*) d_in[1];
    float4*       out   = (float4*)d_out;

    dim3 grid(CHUNKS, 64 * 3);   // 32 chunks x 192 planes = 6144 CTAs
    RandomPixelMapping_19593640805006_kernel<<<grid, THREADS>>>(x, table, out);
}